// round 2
// baseline (speedup 1.0000x reference)
#include <cuda_runtime.h>
#include <math.h>

#define NBINS (1u << 18)      // histogram bins over (float_bits >> 12)
#define BIN_SHIFT 12
#define NCHUNK 256            // NBINS / 1024
#define MAXC (1u << 21)       // max candidates (2M)
#define MAXF 16384            // max finalists
#define TS 2048               // rank-pass shared tile

__device__ unsigned g_ncand;
__device__ unsigned g_nfinal;
__device__ int      g_T;
__device__ unsigned g_hist[NBINS];
__device__ unsigned g_chunk[NCHUNK];
__device__ float    g_cand_val[MAXC];
__device__ int      g_cand_idx[MAXC];
__device__ float    g_fin_val[MAXF];
__device__ int      g_fin_idx[MAXF];

// ---------------------------------------------------------------- init
__global__ void k_init() {
    unsigned i = blockIdx.x * blockDim.x + threadIdx.x;
    if (i < NBINS) g_hist[i] = 0u;
    if (i == 0) { g_ncand = 0u; g_nfinal = 0u; }
}

// ---------------------------------------------------------------- NMS + candidate append + histogram
__device__ __forceinline__ void load_row6(const float* __restrict__ p, int x0, int W, float* r) {
    float4 v = *reinterpret_cast<const float4*>(p + x0);
    r[0] = p[x0 > 0 ? x0 - 1 : 0];
    r[1] = v.x; r[2] = v.y; r[3] = v.z; r[4] = v.w;
    r[5] = p[x0 + 4 < W ? x0 + 4 : W - 1];
}

__global__ void k_nms(const float* __restrict__ low, const float* __restrict__ cur,
                      const float* __restrict__ high, int H, int W) {
    int c = blockIdx.x * blockDim.x + threadIdx.x;
    int X4 = W >> 2;
    if (c >= H * X4) return;
    int y  = c / X4;
    int x0 = (c - y * X4) << 2;
    int ym = y > 0 ? y - 1 : 0;
    int yp = y < H - 1 ? y + 1 : y;

    float r0[6], r1[6], r2[6];
    load_row6(cur + (size_t)ym * W, x0, W, r0);
    load_row6(cur + (size_t)y  * W, x0, W, r1);
    load_row6(cur + (size_t)yp * W, x0, W, r2);
    float4 lo4 = *reinterpret_cast<const float4*>(low  + (size_t)y * W + x0);
    float4 hi4 = *reinterpret_cast<const float4*>(high + (size_t)y * W + x0);
    float lo[4] = {lo4.x, lo4.y, lo4.z, lo4.w};
    float hi[4] = {hi4.x, hi4.y, hi4.z, hi4.w};

    float cm[6];
#pragma unroll
    for (int j = 0; j < 6; j++) cm[j] = fmaxf(r0[j], fmaxf(r1[j], r2[j]));

    bool yok = (y >= 3) && (y < H - 3);
#pragma unroll
    for (int i = 0; i < 4; i++) {
        int x   = x0 + i;
        float v = r1[i + 1];
        float mp = fmaxf(cm[i], fmaxf(cm[i + 1], cm[i + 2]));
        bool cand = yok && (x >= 3) && (x < W - 3) &&
                    (v - mp + 1e-5f > 0.0f) && (v > lo[i]) && (v > hi[i]);
        unsigned am = __activemask();
        unsigned m  = __ballot_sync(am, cand);
        if (cand) {
            int lane   = threadIdx.x & 31;
            int leader = __ffs(m) - 1;
            unsigned pos = 0;
            if (lane == leader) pos = atomicAdd(&g_ncand, (unsigned)__popc(m));
            pos = __shfl_sync(m, pos, leader);
            pos += __popc(m & ((1u << lane) - 1));
            if (pos < MAXC) {
                g_cand_val[pos] = v;
                g_cand_idx[pos] = y * W + x;
            }
            unsigned bin = __float_as_uint(v) >> BIN_SHIFT;
            if (bin >= NBINS) bin = NBINS - 1;
            atomicAdd(&g_hist[bin], 1u);
        }
    }
}

// ---------------------------------------------------------------- chunk sums (256 chunks of 1024 bins)
__global__ void k_chunks() {
    __shared__ unsigned sh[256];
    unsigned t = threadIdx.x, b = blockIdx.x;
    unsigned s = 0;
    for (unsigned i = t; i < 1024; i += 256) s += g_hist[b * 1024 + i];
    sh[t] = s;
    __syncthreads();
    for (int off = 128; off > 0; off >>= 1) {
        if (t < (unsigned)off) sh[t] += sh[t + off];
        __syncthreads();
    }
    if (t == 0) g_chunk[b] = sh[0];
}

// ---------------------------------------------------------------- threshold search (single block)
__global__ void k_thresh(int kk) {
    __shared__ unsigned cs[NCHUNK];
    __shared__ unsigned bs[1024];
    __shared__ int s_chunk;
    __shared__ unsigned s_acc;
    int t = threadIdx.x;
    if (t < NCHUNK) cs[t] = g_chunk[t];
    __syncthreads();
    if (t == 0) {
        unsigned acc = 0;
        int c;
        for (c = NCHUNK - 1; c >= 0; c--) {
            if (acc + cs[c] >= (unsigned)kk) break;
            acc += cs[c];
        }
        if (c < 0) c = 0;
        s_chunk = c; s_acc = acc;
    }
    __syncthreads();
    int c = s_chunk;
    for (int i = t; i < 1024; i += blockDim.x) bs[i] = g_hist[c * 1024 + i];
    __syncthreads();
    if (t == 0) {
        unsigned acc = s_acc;
        int b;
        for (b = 1023; b >= 0; b--) {
            if (acc + bs[b] >= (unsigned)kk) break;
            acc += bs[b];
        }
        if (b < 0) b = 0;
        g_T = c * 1024 + b;
    }
}

// ---------------------------------------------------------------- gather finalists (bin >= T)
__global__ void k_gather() {
    unsigned N = g_ncand;
    if (N > MAXC) N = MAXC;
    int T = g_T;
    unsigned stride = gridDim.x * blockDim.x;
    for (unsigned i = blockIdx.x * blockDim.x + threadIdx.x; i < N; i += stride) {
        float v = g_cand_val[i];
        unsigned bin = __float_as_uint(v) >> BIN_SHIFT;
        if (bin >= NBINS) bin = NBINS - 1;
        bool sel = (int)bin >= T;
        unsigned am = __activemask();
        unsigned m  = __ballot_sync(am, sel);
        if (sel) {
            int lane   = threadIdx.x & 31;
            int leader = __ffs(m) - 1;
            unsigned pos = 0;
            if (lane == leader) pos = atomicAdd(&g_nfinal, (unsigned)__popc(m));
            pos = __shfl_sync(m, pos, leader);
            pos += __popc(m & ((1u << lane) - 1));
            if (pos < MAXF) {
                g_fin_val[pos] = v;
                g_fin_idx[pos] = g_cand_idx[i];
            }
        }
    }
}

// ---------------------------------------------------------------- exact rank + subpixel refine + emit
__global__ void k_rank(const float* __restrict__ low, const float* __restrict__ cur,
                       const float* __restrict__ high, float* __restrict__ out,
                       int H, int W, int k) {
    __shared__ float sv[TS];
    __shared__ int   si[TS];
    int M = (int)min(g_nfinal, (unsigned)MAXF);
    int i = blockIdx.x * blockDim.x + threadIdx.x;
    bool valid = i < M;
    float vi = 0.0f;
    int   di = 0;
    if (valid) { vi = g_fin_val[i]; di = g_fin_idx[i]; }

    unsigned rank = 0;
    for (int base = 0; base < M; base += TS) {
        int n = min(TS, M - base);
        __syncthreads();
        for (int j = threadIdx.x; j < n; j += blockDim.x) {
            sv[j] = g_fin_val[base + j];
            si[j] = g_fin_idx[base + j];
        }
        __syncthreads();
        if (valid) {
            for (int j = 0; j < n; j++) {
                float vj = sv[j];
                rank += (vj > vi || (vj == vi && si[j] < di)) ? 1u : 0u;
            }
        }
    }

    if (valid && rank < (unsigned)k) {
        int y = di / W;
        int x = di - y * W;
        float tot = 0.f, sl = 0.f, shh = 0.f, rp = 0.f, rm = 0.f, cp = 0.f, cmm = 0.f;
        const float* planes[3] = {low, cur, high};
#pragma unroll
        for (int p = 0; p < 3; p++) {
            const float* P = planes[p];
            float ps = 0.f;
#pragma unroll
            for (int dy = -1; dy <= 1; dy++) {
#pragma unroll
                for (int dx = -1; dx <= 1; dx++) {
                    float a = P[(size_t)(y + dy) * W + (x + dx)];
                    ps += a;
                    if (dy ==  1) rp  += a;
                    if (dy == -1) rm  += a;
                    if (dx ==  1) cp  += a;
                    if (dx == -1) cmm += a;
                }
            }
            tot += ps;
            if (p == 0) sl  = ps;
            if (p == 2) shh = ps;
        }
        float den = tot + 1e-8f;
        float s  = (shh - sl) / den;
        float ys = ((rp - rm) / den + (float)y) / (float)H;
        float xs = ((cp - cmm) / den + (float)x) / (float)W;
        float a  = s * (1.0f / (float)(H < W ? H : W));

        out[rank] = vi;
        float* A = out + k + (size_t)rank * 6;
        A[0] = a;    A[1] = 0.0f; A[2] = xs;
        A[3] = 0.0f; A[4] = a;    A[5] = ys;
    }
}

// ---------------------------------------------------------------- launch
extern "C" void kernel_launch(void* const* d_in, const int* in_sizes, int n_in,
                              void* d_out, int out_size) {
    const float* low  = (const float*)d_in[0];
    const float* cur  = (const float*)d_in[1];
    const float* high = (const float*)d_in[2];
    float* out = (float*)d_out;

    int HW = in_sizes[0];
    int W  = (int)(sqrt((double)HW) + 0.5);
    int H  = HW / W;
    int k  = out_size / 7;   // out = k topk values + k*6 full_A entries

    k_init<<<(NBINS + 255) / 256, 256>>>();

    int X4 = W >> 2;
    int total = H * X4;
    k_nms<<<(total + 255) / 256, 256>>>(low, cur, high, H, W);

    k_chunks<<<NCHUNK, 256>>>();
    k_thresh<<<1, 256>>>(k);
    k_gather<<<1024, 256>>>();
    k_rank<<<MAXF / 256, 256>>>(low, cur, high, out, H, W, k);
}

// round 4
// speedup vs baseline: 1.0275x; 1.0275x over previous
#include <cuda_runtime.h>
#include <math.h>

#define NBINS (1u << 18)      // histogram bins over (float_bits >> 12)
#define BIN_SHIFT 12
#define NCHUNK 256            // NBINS / 1024
#define MAXC (1u << 21)       // max candidates (2M)
#define MAXF 16384            // max finalists
#define TS 2048               // rank-pass shared tile

__device__ unsigned g_ncand;
__device__ unsigned g_nfinal;
__device__ int      g_T;
__device__ unsigned g_hist[NBINS];
__device__ unsigned g_chunk[NCHUNK];
__device__ float    g_cand_val[MAXC];
__device__ int      g_cand_idx[MAXC];
__device__ float    g_fin_val[MAXF];
__device__ int      g_fin_idx[MAXF];

// ---------------------------------------------------------------- init
__global__ void k_init() {
    unsigned i = blockIdx.x * blockDim.x + threadIdx.x;
    if (i < NBINS) g_hist[i] = 0u;
    if (i == 0) { g_ncand = 0u; g_nfinal = 0u; }
}

// ---------------------------------------------------------------- NMS + candidate append + histogram
__device__ __forceinline__ void load_row6(const float* __restrict__ p, int x0, int W, float* r) {
    float4 v = *reinterpret_cast<const float4*>(p + x0);
    r[0] = p[x0 > 0 ? x0 - 1 : 0];
    r[1] = v.x; r[2] = v.y; r[3] = v.z; r[4] = v.w;
    r[5] = p[x0 + 4 < W ? x0 + 4 : W - 1];
}

__global__ void __launch_bounds__(256) k_nms(
        const float* __restrict__ low, const float* __restrict__ cur,
        const float* __restrict__ high, int H, int W) {
    __shared__ unsigned swc[8];
    __shared__ unsigned sbase;

    int c = blockIdx.x * blockDim.x + threadIdx.x;
    int X4 = W >> 2;
    bool in_range = c < H * X4;

    float vals[4];
    int   idxs[4];
    int   nc = 0;

    if (in_range) {
        int y  = c / X4;
        int x0 = (c - y * X4) << 2;
        int ym = y > 0 ? y - 1 : 0;
        int yp = y < H - 1 ? y + 1 : y;

        float r0[6], r1[6], r2[6];
        load_row6(cur + (size_t)ym * W, x0, W, r0);
        load_row6(cur + (size_t)y  * W, x0, W, r1);
        load_row6(cur + (size_t)yp * W, x0, W, r2);
        float4 lo4 = *reinterpret_cast<const float4*>(low  + (size_t)y * W + x0);
        float4 hi4 = *reinterpret_cast<const float4*>(high + (size_t)y * W + x0);
        float lo[4] = {lo4.x, lo4.y, lo4.z, lo4.w};
        float hi[4] = {hi4.x, hi4.y, hi4.z, hi4.w};

        float cm[6];
#pragma unroll
        for (int j = 0; j < 6; j++) cm[j] = fmaxf(r0[j], fmaxf(r1[j], r2[j]));

        bool yok = (y >= 3) && (y < H - 3);
#pragma unroll
        for (int i = 0; i < 4; i++) {
            int x   = x0 + i;
            float v = r1[i + 1];
            float mp = fmaxf(cm[i], fmaxf(cm[i + 1], cm[i + 2]));
            bool cand = yok && (x >= 3) && (x < W - 3) &&
                        (v - mp + 1e-5f > 0.0f) && (v > lo[i]) && (v > hi[i]);
            if (cand) {
                vals[nc] = v;
                idxs[nc] = y * W + x;
                nc++;
                unsigned bin = __float_as_uint(v) >> BIN_SHIFT;
                if (bin >= NBINS) bin = NBINS - 1;
                atomicAdd(&g_hist[bin], 1u);
            }
        }
    }

    // ---- block-aggregated append: exactly ONE atomicAdd(g_ncand) per block
    int lane = threadIdx.x & 31;
    int wid  = threadIdx.x >> 5;
    int pre  = nc;                               // inclusive warp scan
#pragma unroll
    for (int off = 1; off < 32; off <<= 1) {
        int t = __shfl_up_sync(0xffffffffu, pre, off);
        if (lane >= off) pre += t;
    }
    int ex = pre - nc;                           // exclusive within warp
    if (lane == 31) swc[wid] = (unsigned)pre;    // warp total
    __syncthreads();
    if (threadIdx.x == 0) {
        unsigned tot = 0;
#pragma unroll
        for (int w = 0; w < 8; w++) { unsigned t = swc[w]; swc[w] = tot; tot += t; }
        sbase = tot ? atomicAdd(&g_ncand, tot) : 0u;
    }
    __syncthreads();
    unsigned base = sbase + swc[wid] + (unsigned)ex;
#pragma unroll
    for (int j = 0; j < 4; j++) {
        if (j < nc) {
            unsigned p = base + j;
            if (p < MAXC) {
                g_cand_val[p] = vals[j];
                g_cand_idx[p] = idxs[j];
            }
        }
    }
}

// ---------------------------------------------------------------- chunk sums (256 chunks of 1024 bins)
__global__ void k_chunks() {
    __shared__ unsigned sh[256];
    unsigned t = threadIdx.x, b = blockIdx.x;
    unsigned s = 0;
    for (unsigned i = t; i < 1024; i += 256) s += g_hist[b * 1024 + i];
    sh[t] = s;
    __syncthreads();
    for (int off = 128; off > 0; off >>= 1) {
        if (t < (unsigned)off) sh[t] += sh[t + off];
        __syncthreads();
    }
    if (t == 0) g_chunk[b] = sh[0];
}

// ---------------------------------------------------------------- threshold search (1024-thread parallel scans)
__global__ void __launch_bounds__(1024) k_thresh(int kk) {
    __shared__ unsigned s[1024];
    __shared__ int s_c;
    __shared__ unsigned s_acc;
    __shared__ int s_b;
    int t = threadIdx.x;
    unsigned K = (unsigned)kk;

    // ---- stage 1: suffix sums over 256 chunks (reversed inclusive scan)
    if (t < 256) s[t] = g_chunk[255 - t];
    __syncthreads();
#pragma unroll
    for (int off = 1; off < 256; off <<= 1) {
        unsigned add = (t < 256 && t >= off) ? s[t - off] : 0u;
        __syncthreads();
        if (t < 256) s[t] += add;
        __syncthreads();
    }
    // s[r] = sum of top (r+1) chunks, nondecreasing in r. Find min r with s[r] >= K.
    if (t == 0) {            // fallback: total < K
        if (s[255] < K) { s_c = 0; s_acc = s[254]; }
    }
    if (t < 256 && s[t] >= K && (t == 0 || s[t - 1] < K)) {
        s_c = 255 - t;
        s_acc = (t == 0) ? 0u : s[t - 1];
    }
    __syncthreads();
    int c = s_c;
    unsigned acc = s_acc;
    __syncthreads();

    // ---- stage 2: suffix sums over 1024 bins of chunk c
    s[t] = g_hist[c * 1024 + (1023 - t)];
    __syncthreads();
#pragma unroll
    for (int off = 1; off < 1024; off <<= 1) {
        unsigned add = (t >= off) ? s[t - off] : 0u;
        __syncthreads();
        s[t] += add;
        __syncthreads();
    }
    if (t == 0) s_b = 0;     // fallback
    __syncthreads();
    if (acc + s[t] >= K && (t == 0 || acc + s[t - 1] < K))
        s_b = 1023 - t;
    __syncthreads();
    if (t == 0) g_T = c * 1024 + s_b;
}

// ---------------------------------------------------------------- gather finalists (bin >= T)
__global__ void k_gather() {
    unsigned N = g_ncand;
    if (N > MAXC) N = MAXC;
    int T = g_T;
    unsigned stride = gridDim.x * blockDim.x;
    for (unsigned i = blockIdx.x * blockDim.x + threadIdx.x; i < N; i += stride) {
        float v = g_cand_val[i];
        unsigned bin = __float_as_uint(v) >> BIN_SHIFT;
        if (bin >= NBINS) bin = NBINS - 1;
        bool sel = (int)bin >= T;
        unsigned am = __activemask();
        unsigned m  = __ballot_sync(am, sel);
        if (sel) {
            int lane   = threadIdx.x & 31;
            int leader = __ffs(m) - 1;
            unsigned pos = 0;
            if (lane == leader) pos = atomicAdd(&g_nfinal, (unsigned)__popc(m));
            pos = __shfl_sync(m, pos, leader);
            pos += __popc(m & ((1u << lane) - 1));
            if (pos < MAXF) {
                g_fin_val[pos] = v;
                g_fin_idx[pos] = g_cand_idx[i];
            }
        }
    }
}

// ---------------------------------------------------------------- exact rank + subpixel refine + emit
__global__ void k_rank(const float* __restrict__ low, const float* __restrict__ cur,
                       const float* __restrict__ high, float* __restrict__ out,
                       int H, int W, int k) {
    __shared__ float sv[TS];
    __shared__ int   si[TS];
    int M = (int)min(g_nfinal, (unsigned)MAXF);
    int i = blockIdx.x * blockDim.x + threadIdx.x;
    bool valid = i < M;
    float vi = 0.0f;
    int   di = 0;
    if (valid) { vi = g_fin_val[i]; di = g_fin_idx[i]; }

    unsigned rank = 0;
    for (int base = 0; base < M; base += TS) {
        int n = min(TS, M - base);
        __syncthreads();
        for (int j = threadIdx.x; j < n; j += blockDim.x) {
            sv[j] = g_fin_val[base + j];
            si[j] = g_fin_idx[base + j];
        }
        __syncthreads();
        if (valid) {
            for (int j = 0; j < n; j++) {
                float vj = sv[j];
                rank += (vj > vi || (vj == vi && si[j] < di)) ? 1u : 0u;
            }
        }
    }

    if (valid && rank < (unsigned)k) {
        int y = di / W;
        int x = di - y * W;
        float tot = 0.f, sl = 0.f, shh = 0.f, rp = 0.f, rm = 0.f, cp = 0.f, cmm = 0.f;
        const float* planes[3] = {low, cur, high};
#pragma unroll
        for (int p = 0; p < 3; p++) {
            const float* P = planes[p];
            float ps = 0.f;
#pragma unroll
            for (int dy = -1; dy <= 1; dy++) {
#pragma unroll
                for (int dx = -1; dx <= 1; dx++) {
                    float a = P[(size_t)(y + dy) * W + (x + dx)];
                    ps += a;
                    if (dy ==  1) rp  += a;
                    if (dy == -1) rm  += a;
                    if (dx ==  1) cp  += a;
                    if (dx == -1) cmm += a;
                }
            }
            tot += ps;
            if (p == 0) sl  = ps;
            if (p == 2) shh = ps;
        }
        float den = tot + 1e-8f;
        float s  = (shh - sl) / den;
        float ys = ((rp - rm) / den + (float)y) / (float)H;
        float xs = ((cp - cmm) / den + (float)x) / (float)W;
        float a  = s * (1.0f / (float)(H < W ? H : W));

        out[rank] = vi;
        float* A = out + k + (size_t)rank * 6;
        A[0] = a;    A[1] = 0.0f; A[2] = xs;
        A[3] = 0.0f; A[4] = a;    A[5] = ys;
    }
}

// ---------------------------------------------------------------- launch
extern "C" void kernel_launch(void* const* d_in, const int* in_sizes, int n_in,
                              void* d_out, int out_size) {
    const float* low  = (const float*)d_in[0];
    const float* cur  = (const float*)d_in[1];
    const float* high = (const float*)d_in[2];
    float* out = (float*)d_out;

    int HW = in_sizes[0];
    int W  = (int)(sqrt((double)HW) + 0.5);
    int H  = HW / W;
    int k  = out_size / 7;   // out = k topk values + k*6 full_A entries

    k_init<<<(NBINS + 255) / 256, 256>>>();

    int X4 = W >> 2;
    int total = H * X4;
    k_nms<<<(total + 255) / 256, 256>>>(low, cur, high, H, W);

    k_chunks<<<NCHUNK, 256>>>();
    k_thresh<<<1, 1024>>>(k);
    k_gather<<<1024, 256>>>();
    k_rank<<<MAXF / 256, 256>>>(low, cur, high, out, H, W, k);
}

// round 5
// speedup vs baseline: 1.0576x; 1.0293x over previous
#include <cuda_runtime.h>
#include <math.h>

#define NBINS (1u << 18)      // histogram bins over (float_bits >> 12)
#define BIN_SHIFT 12
#define NCHUNK 256            // NBINS / 1024
#define MAXC (1u << 21)       // max candidates (2M)
#define MAXF 16384            // max finalists
#define NB 592                // 148 SMs x 4 resident blocks
#define NT 256
#define TS 1024               // rank-pass shared tile

__device__ unsigned g_ncand;
__device__ unsigned g_nfinal;
__device__ unsigned g_barrier;
__device__ int      g_T;
__device__ unsigned g_hist[NBINS];
__device__ unsigned g_chunk[NCHUNK];
__device__ float    g_cand_val[MAXC];
__device__ int      g_cand_idx[MAXC];
__device__ float    g_fin_val[MAXF];
__device__ int      g_fin_idx[MAXF];

// ---------------------------------------------------------------- init (per launch)
__global__ void k_init() {
    unsigned i = blockIdx.x * blockDim.x + threadIdx.x;
    if (i < NBINS) g_hist[i] = 0u;
    if (i == 0) { g_ncand = 0u; g_nfinal = 0u; g_barrier = 0u; }
}

// ---------------------------------------------------------------- software grid barrier
__device__ __forceinline__ void gbar(unsigned target) {
    __syncthreads();
    if (threadIdx.x == 0) {
        __threadfence();
        atomicAdd(&g_barrier, 1u);
        while (*(volatile unsigned*)&g_barrier < target) __nanosleep(64);
        __threadfence();
    }
    __syncthreads();
}

__device__ __forceinline__ void load_row6(const float* __restrict__ p, int x0, int W, float* r) {
    float4 v = *reinterpret_cast<const float4*>(p + x0);
    r[0] = p[x0 > 0 ? x0 - 1 : 0];
    r[1] = v.x; r[2] = v.y; r[3] = v.z; r[4] = v.w;
    r[5] = p[x0 + 4 < W ? x0 + 4 : W - 1];
}

// ---------------------------------------------------------------- fused persistent kernel
__global__ void __launch_bounds__(NT, 4) k_mega(
        const float* __restrict__ low, const float* __restrict__ cur,
        const float* __restrict__ high, float* __restrict__ out,
        int H, int W, int k) {
    __shared__ unsigned sh[2 * TS];   // 8 KB, reused across phases
    __shared__ int s_c;
    __shared__ unsigned s_acc;
    __shared__ int s_b;

    const int tid  = threadIdx.x;
    const int lane = tid & 31;
    const int wid  = tid >> 5;
    const unsigned gid = blockIdx.x * NT + tid;
    const unsigned gsz = NB * NT;
    const unsigned K = (unsigned)k;

    // ================= phase 1: NMS + histogram + candidate append =================
    const int X4 = W >> 2;
    const int total = H * X4;
    const int iters = (total + (int)gsz - 1) / (int)gsz;

    for (int it = 0; it < iters; it++) {
        int c = (int)gid + it * (int)gsz;
        bool in_range = c < total;

        float vals[4];
        int   idxs[4];
        int   nc = 0;

        if (in_range) {
            int y  = c / X4;
            int x0 = (c - y * X4) << 2;
            int ym = y > 0 ? y - 1 : 0;
            int yp = y < H - 1 ? y + 1 : y;

            float r0[6], r1[6], r2[6];
            load_row6(cur + (size_t)ym * W, x0, W, r0);
            load_row6(cur + (size_t)y  * W, x0, W, r1);
            load_row6(cur + (size_t)yp * W, x0, W, r2);
            float4 lo4 = *reinterpret_cast<const float4*>(low  + (size_t)y * W + x0);
            float4 hi4 = *reinterpret_cast<const float4*>(high + (size_t)y * W + x0);
            float lo[4] = {lo4.x, lo4.y, lo4.z, lo4.w};
            float hi[4] = {hi4.x, hi4.y, hi4.z, hi4.w};

            float cm[6];
#pragma unroll
            for (int j = 0; j < 6; j++) cm[j] = fmaxf(r0[j], fmaxf(r1[j], r2[j]));

            bool yok = (y >= 3) && (y < H - 3);
#pragma unroll
            for (int i = 0; i < 4; i++) {
                int x   = x0 + i;
                float v = r1[i + 1];
                float mp = fmaxf(cm[i], fmaxf(cm[i + 1], cm[i + 2]));
                bool cand = yok && (x >= 3) && (x < W - 3) &&
                            (v - mp + 1e-5f > 0.0f) && (v > lo[i]) && (v > hi[i]);
                if (cand) {
                    vals[nc] = v;
                    idxs[nc] = y * W + x;
                    nc++;
                    unsigned bin = __float_as_uint(v) >> BIN_SHIFT;
                    if (bin >= NBINS) bin = NBINS - 1;
                    atomicAdd(&g_hist[bin], 1u);
                }
            }
        }

        // block-aggregated append (one g_ncand atomic per block-iteration)
        int pre = nc;
#pragma unroll
        for (int off = 1; off < 32; off <<= 1) {
            int t = __shfl_up_sync(0xffffffffu, pre, off);
            if (lane >= off) pre += t;
        }
        int ex = pre - nc;
        if (lane == 31) sh[wid] = (unsigned)pre;
        __syncthreads();
        if (tid == 0) {
            unsigned tot = 0;
#pragma unroll
            for (int w = 0; w < 8; w++) { unsigned t = sh[w]; sh[w] = tot; tot += t; }
            sh[8] = tot ? atomicAdd(&g_ncand, tot) : 0u;
        }
        __syncthreads();
        unsigned base = sh[8] + sh[wid] + (unsigned)ex;
#pragma unroll
        for (int j = 0; j < 4; j++) {
            if (j < nc) {
                unsigned p = base + j;
                if (p < MAXC) {
                    g_cand_val[p] = vals[j];
                    g_cand_idx[p] = idxs[j];
                }
            }
        }
        __syncthreads();   // protect sh reuse next iteration
    }

    gbar(NB);

    // ================= phase 2: chunk sums (blocks 0..255) =================
    if (blockIdx.x < NCHUNK) {
        unsigned s = 0;
#pragma unroll
        for (int i = tid; i < 1024; i += NT) s += g_hist[blockIdx.x * 1024 + i];
        sh[tid] = s;
        __syncthreads();
        for (int off = 128; off > 0; off >>= 1) {
            if (tid < off) sh[tid] += sh[tid + off];
            __syncthreads();
        }
        if (tid == 0) g_chunk[blockIdx.x] = sh[0];
    }

    gbar(2u * NB);

    // ================= phase 3: threshold (block 0) =================
    if (blockIdx.x == 0) {
        // stage 1: suffix sums over 256 chunks (descending order)
        sh[tid] = g_chunk[255 - tid];
        __syncthreads();
        for (int off = 1; off < 256; off <<= 1) {
            unsigned add = (tid >= off) ? sh[tid - off] : 0u;
            __syncthreads();
            sh[tid] += add;
            __syncthreads();
        }
        if (tid == 0) {
            s_c = 0;
            s_acc = (sh[255] < K) ? sh[254] : 0u;   // fallback: total < K
        }
        __syncthreads();
        if (sh[tid] >= K && (tid == 0 || sh[tid - 1] < K)) {
            s_c = 255 - tid;
            s_acc = tid ? sh[tid - 1] : 0u;
        }
        __syncthreads();
        int cch = s_c;
        unsigned acc = s_acc;
        __syncthreads();

        // stage 2: 1024 bins of chunk cch, 4 per thread, descending
        unsigned a[4], p[4];
#pragma unroll
        for (int j = 0; j < 4; j++)
            a[j] = g_hist[cch * 1024 + (1023 - (4 * tid + j))];
        p[0] = a[0]; p[1] = p[0] + a[1]; p[2] = p[1] + a[2]; p[3] = p[2] + a[3];
        sh[tid] = p[3];
        __syncthreads();
        for (int off = 1; off < 256; off <<= 1) {
            unsigned add = (tid >= off) ? sh[tid - off] : 0u;
            __syncthreads();
            sh[tid] += add;
            __syncthreads();
        }
        unsigned excl = sh[tid] - p[3];
        if (tid == 0) s_b = 0;
        __syncthreads();
        unsigned prev = acc + excl;
#pragma unroll
        for (int j = 0; j < 4; j++) {
            unsigned cj = acc + excl + p[j];
            if (cj >= K && prev < K) s_b = 1023 - (4 * tid + j);
            prev = cj;
        }
        __syncthreads();
        if (tid == 0) g_T = cch * 1024 + s_b;
    }

    gbar(3u * NB);

    // ================= phase 4: gather finalists =================
    {
        unsigned N = g_ncand;
        if (N > MAXC) N = MAXC;
        int T = g_T;
        for (unsigned i = gid; i < N; i += gsz) {
            float v = g_cand_val[i];
            unsigned bin = __float_as_uint(v) >> BIN_SHIFT;
            if (bin >= NBINS) bin = NBINS - 1;
            bool sel = (int)bin >= T;
            unsigned am = __activemask();
            unsigned m  = __ballot_sync(am, sel);
            if (sel) {
                int leader = __ffs(m) - 1;
                unsigned pos = 0;
                if (lane == leader) pos = atomicAdd(&g_nfinal, (unsigned)__popc(m));
                pos = __shfl_sync(m, pos, leader);
                pos += __popc(m & ((1u << lane) - 1));
                if (pos < MAXF) {
                    g_fin_val[pos] = v;
                    g_fin_idx[pos] = g_cand_idx[i];
                }
            }
        }
    }

    gbar(4u * NB);

    // ================= phase 5: exact rank + subpixel refine + emit (blocks 0..63) =================
    if (blockIdx.x >= MAXF / NT) return;

    float* sv = (float*)sh;
    int*   si = (int*)&sh[TS];
    int M = (int)min(g_nfinal, (unsigned)MAXF);
    int i = blockIdx.x * NT + tid;
    bool valid = i < M;
    float vi = 0.0f;
    int   di = 0;
    if (valid) { vi = g_fin_val[i]; di = g_fin_idx[i]; }

    unsigned rank = 0;
    for (int base = 0; base < M; base += TS) {
        int n = min(TS, M - base);
        __syncthreads();
        for (int j = tid; j < n; j += NT) {
            sv[j] = g_fin_val[base + j];
            si[j] = g_fin_idx[base + j];
        }
        __syncthreads();
        if (valid) {
            for (int j = 0; j < n; j++) {
                float vj = sv[j];
                rank += (vj > vi || (vj == vi && si[j] < di)) ? 1u : 0u;
            }
        }
    }

    if (valid && rank < (unsigned)k) {
        int y = di / W;
        int x = di - y * W;
        float tot = 0.f, sl = 0.f, shh = 0.f, rp = 0.f, rm = 0.f, cp = 0.f, cmm = 0.f;
        const float* planes[3] = {low, cur, high};
#pragma unroll
        for (int p2 = 0; p2 < 3; p2++) {
            const float* P = planes[p2];
            float ps = 0.f;
#pragma unroll
            for (int dy = -1; dy <= 1; dy++) {
#pragma unroll
                for (int dx = -1; dx <= 1; dx++) {
                    float a = P[(size_t)(y + dy) * W + (x + dx)];
                    ps += a;
                    if (dy ==  1) rp  += a;
                    if (dy == -1) rm  += a;
                    if (dx ==  1) cp  += a;
                    if (dx == -1) cmm += a;
                }
            }
            tot += ps;
            if (p2 == 0) sl  = ps;
            if (p2 == 2) shh = ps;
        }
        float den = tot + 1e-8f;
        float s  = (shh - sl) / den;
        float ys = ((rp - rm) / den + (float)y) / (float)H;
        float xs = ((cp - cmm) / den + (float)x) / (float)W;
        float a  = s * (1.0f / (float)(H < W ? H : W));

        out[rank] = vi;
        float* A = out + k + (size_t)rank * 6;
        A[0] = a;    A[1] = 0.0f; A[2] = xs;
        A[3] = 0.0f; A[4] = a;    A[5] = ys;
    }
}

// ---------------------------------------------------------------- launch
extern "C" void kernel_launch(void* const* d_in, const int* in_sizes, int n_in,
                              void* d_out, int out_size) {
    const float* low  = (const float*)d_in[0];
    const float* cur  = (const float*)d_in[1];
    const float* high = (const float*)d_in[2];
    float* out = (float*)d_out;

    int HW = in_sizes[0];
    int W  = (int)(sqrt((double)HW) + 0.5);
    int H  = HW / W;
    int k  = out_size / 7;   // out = k topk values + k*6 full_A entries

    k_init<<<(NBINS + 255) / 256, 256>>>();
    k_mega<<<NB, NT>>>(low, cur, high, out, H, W, k);
}